// round 13
// baseline (speedup 1.0000x reference)
#include <cuda_runtime.h>
#include <cstdint>

#define Bn   4
#define Ln   8
#define Nn   2048
#define Cn   32
#define MIDn 64
#define OUTn 128
#define Mn   1024
#define KSn  32
#define KMn  192
#define BLn  32
#define FLTMAXC 3.4028234663852886e38f

#define MUL2(out, a, b) asm("mul.rn.f32x2 %0, %1, %2;" : "=l"(out) : "l"(a), "l"(b))
#define ADD2(out, a, b) asm("add.rn.f32x2 %0, %1, %2;" : "=l"(out) : "l"(a), "l"(b))
#define FMA2(out, a, b, c) asm("fma.rn.f32x2 %0, %1, %2, %3;" : "=l"(out) : "l"(a), "l"(b), "l"(c))
#define PACK2(out, lo, hi) asm("mov.b64 %0, {%1, %2};" : "=l"(out) : "r"(lo), "r"(hi))
#define UNPACK2(lo, hi, in) asm("mov.b64 {%0, %1}, %2;" : "=r"(lo), "=r"(hi) : "l"(in))

__device__ float g_ft[BLn * Nn * Cn];
__device__ float g_x[Bn * Ln * KMn * Mn];
__device__ float g_W2[MIDn * 96];
__device__ float g_mean[Ln * KMn];
__device__ float g_rstd[Ln * KMn];

__global__ void nop_kernel() {}

// ---------------------------------------------------------------------------
// 1) Transpose features (B,L,C,N) -> g_ft[frame][n][c]; block(0,0) builds W2
// ---------------------------------------------------------------------------
__global__ void transpose_feat_kernel(const float* __restrict__ feat,
                                      const float* __restrict__ cdw,
                                      const float* __restrict__ cfw) {
    __shared__ float sm[32][33];
    int f  = blockIdx.y;
    int n0 = blockIdx.x * 32;
    int tx = threadIdx.x, ty = threadIdx.y;
    sm[ty][tx] = feat[((size_t)f * Cn + ty) * Nn + n0 + tx];
    if (blockIdx.x == 0 && blockIdx.y == 0) {
        int tid = ty * 32 + tx;
        for (int idx = tid; idx < MIDn * 96; idx += 1024) {
            int oo = idx / 96, r = idx % 96, c = r / 3, d = r % 3;
            g_W2[idx] = cfw[oo * Cn + c] * cdw[oo * 3 + d];
        }
    }
    __syncthreads();
    g_ft[((size_t)f * Nn + n0 + ty) * Cn + tx] = sm[tx][ty];
}

// ---------------------------------------------------------------------------
// 2) FPS: 32 blocks x 128 threads (4 warps), 16 points/thread, f32x2 packed.
// ---------------------------------------------------------------------------
__global__ void __launch_bounds__(128)
fps_kernel(const float* __restrict__ xyz, float* __restrict__ dout) {
    __shared__ float4 pts[Nn];
    __shared__ float  anch[Mn * 3];
    __shared__ unsigned long long pk[2][4];

    int f = blockIdx.x;
    int tid = threadIdx.x, lane = tid & 31;
    int wid = tid >> 5;

    const float* base = xyz + (size_t)f * Nn * 3;
    for (int p = tid; p < Nn; p += 128)
        pts[p] = make_float4(base[3*p], base[3*p+1], base[3*p+2], 0.f);
    __syncthreads();

    unsigned long long px2[8], py2[8], pz2[8];
    float md[16];
#pragma unroll
    for (int q = 0; q < 8; ++q) {
        float4 a = pts[tid + (2*q) * 128];
        float4 b = pts[tid + (2*q+1) * 128];
        PACK2(px2[q], __float_as_uint(a.x), __float_as_uint(b.x));
        PACK2(py2[q], __float_as_uint(a.y), __float_as_uint(b.y));
        PACK2(pz2[q], __float_as_uint(a.z), __float_as_uint(b.z));
        md[2*q] = FLTMAXC; md[2*q+1] = FLTMAXC;
    }
    float sx = pts[0].x, sy = pts[0].y, sz = pts[0].z;

    for (int i = 0; i < Mn; ++i) {
        if (tid == 0) { anch[3*i] = sx; anch[3*i+1] = sy; anch[3*i+2] = sz; }

        unsigned long long nsx2, nsy2, nsz2;
        unsigned nx = __float_as_uint(-sx), ny = __float_as_uint(-sy), nz = __float_as_uint(-sz);
        PACK2(nsx2, nx, nx); PACK2(nsy2, ny, ny); PACK2(nsz2, nz, nz);

        float nv[16];
#pragma unroll
        for (int q = 0; q < 8; ++q) {
            unsigned long long dx, dy, dz, zz, d2;
            ADD2(dx, px2[q], nsx2);
            ADD2(dy, py2[q], nsy2);
            ADD2(dz, pz2[q], nsz2);
            MUL2(zz, dz, dz);
            FMA2(d2, dy, dy, zz);
            FMA2(d2, dx, dx, d2);
            unsigned ulo, uhi;
            UNPACK2(ulo, uhi, d2);
            float nmlo = fminf(md[2*q],   __uint_as_float(ulo));
            float nmhi = fminf(md[2*q+1], __uint_as_float(uhi));
            md[2*q] = nmlo; md[2*q+1] = nmhi;
            nv[2*q] = nmlo; nv[2*q+1] = nmhi;
        }
        float tv[8]; int ti[8];
#pragma unroll
        for (int q = 0; q < 8; ++q) {
            bool c = nv[2*q] >= nv[2*q+1];
            tv[q] = c ? nv[2*q] : nv[2*q+1];
            ti[q] = c ? 2*q : 2*q+1;
        }
#pragma unroll
        for (int q = 0; q < 4; ++q) {
            bool c = tv[2*q] >= tv[2*q+1];
            tv[q] = c ? tv[2*q] : tv[2*q+1];
            ti[q] = c ? ti[2*q] : ti[2*q+1];
        }
        bool c0 = tv[0] >= tv[1];
        float va = c0 ? tv[0] : tv[1];
        int   ia = c0 ? ti[0] : ti[1];
        bool c1 = tv[2] >= tv[3];
        float vb = c1 ? tv[2] : tv[3];
        int   ib = c1 ? ti[2] : ti[3];
        bool cf = va >= vb;
        float bvv = cf ? va : vb;
        int   bj  = cf ? ia : ib;
        unsigned bi = (unsigned)(tid + bj * 128);

        unsigned vbits = __float_as_uint(bvv);
        unsigned wmax  = __reduce_max_sync(0xffffffffu, vbits);
        unsigned cidx  = (vbits == wmax) ? bi : 0xffffffffu;
        unsigned widx  = __reduce_min_sync(0xffffffffu, cidx);

        int s = i & 1;
        if (lane == 0)
            pk[s][wid] = ((unsigned long long)wmax << 32) |
                         (unsigned long long)(~widx);
        __syncthreads();

        unsigned long long m0 = pk[s][0], m1 = pk[s][1];
        unsigned long long m2 = pk[s][2], m3 = pk[s][3];
        unsigned long long ma = (m0 > m1) ? m0 : m1;
        unsigned long long mb = (m2 > m3) ? m2 : m3;
        unsigned long long mm = (ma > mb) ? ma : mb;
        int idx = (int)(~(unsigned)mm);
        float4 spv = pts[idx];
        sx = spv.x; sy = spv.y; sz = spv.z;
    }
    __syncthreads();
    float* o = dout + (size_t)f * Mn * 3;
    const float4* a4 = (const float4*)anch;
    for (int p = tid; p < (Mn * 3) / 4; p += 128)
        ((float4*)o)[p] = a4[p];
}

// ---------------------------------------------------------------------------
// 3) Ball query + grouped conv. 128-anchor tiles, 8 anchors/warp, f32x2
//    pair distances with per-pair skip; GEMM packed over k in f32x2.
// ---------------------------------------------------------------------------
__global__ void __launch_bounds__(512)
group_conv_kernel(const float* __restrict__ xyz,
                  const float* __restrict__ anchors)
{
    extern __shared__ char smraw[];
    float4* npts = (float4*)smraw;                  // 32768 B
    float*  Ssm  = (float*)(smraw + 32768);         // 128*96*4 = 49152 B
    int*    cand = (int*)(smraw + 32768 + 49152);   // 16 w * 256 * 4 = 16384 B

    int tile = blockIdx.x;   // 8 tiles of 128 anchors
    int o    = blockIdx.y;
    int f    = blockIdx.z;
    int b = f >> 3, l = f & 7;
    int tid = threadIdx.x, lane = tid & 31, wid = tid >> 5;

    int ln = l + o - 1;
    if (ln < 0 || ln >= Ln) {
        for (int idx = tid; idx < MIDn * 128; idx += 512) {
            int kk = idx >> 7, mm = idx & 127;
            g_x[((size_t)f * KMn + o * MIDn + kk) * Mn + tile * 128 + mm] = 0.f;
        }
        return;
    }
    int nbr = b * Ln + ln;

    const float* nb = xyz + (size_t)nbr * Nn * 3;
    for (int p = tid; p < Nn; p += 512)
        npts[p] = make_float4(nb[3*p], nb[3*p+1], nb[3*p+2], 0.f);
    __syncthreads();

    int* candw = cand + wid * 256;   // 8 anchors x 32 slots
    const float* fb = g_ft + (size_t)nbr * Nn * Cn;
    unsigned lm = (1u << lane) - 1u;
    const float* abase = anchors + ((size_t)f * Mn + tile * 128 + wid * 8) * 3;

    // --- joint ball query: 8 anchors as 4 packed f32x2 pairs ---
    unsigned long long naxp[4], nayp[4], nazp[4];
    int cnt[8];
#pragma unroll
    for (int p = 0; p < 4; ++p) {
        PACK2(naxp[p], __float_as_uint(-abase[6*p    ]), __float_as_uint(-abase[6*p + 3]));
        PACK2(nayp[p], __float_as_uint(-abase[6*p + 1]), __float_as_uint(-abase[6*p + 4]));
        PACK2(nazp[p], __float_as_uint(-abase[6*p + 2]), __float_as_uint(-abase[6*p + 5]));
        cnt[2*p] = 0; cnt[2*p + 1] = 0;
    }
    for (int basej = 0; basej < Nn; basej += 32) {
        int cmin = cnt[0];
#pragma unroll
        for (int aa = 1; aa < 8; ++aa) cmin = cnt[aa] < cmin ? cnt[aa] : cmin;
        if (cmin >= KSn) break;   // warp-uniform: all pairs done
        int j = basej + lane;
        float4 pt = npts[j];
        unsigned long long pxx, pyy, pzz;
        PACK2(pxx, __float_as_uint(pt.x), __float_as_uint(pt.x));
        PACK2(pyy, __float_as_uint(pt.y), __float_as_uint(pt.y));
        PACK2(pzz, __float_as_uint(pt.z), __float_as_uint(pt.z));
#pragma unroll
        for (int p = 0; p < 4; ++p) {
            if (cnt[2*p] >= KSn && cnt[2*p + 1] >= KSn) continue;  // warp-uniform
            unsigned long long dx, dy, dz, zz, d2;
            ADD2(dx, pxx, naxp[p]);           // p - a (exact: a + (-b))
            ADD2(dy, pyy, nayp[p]);
            ADD2(dz, pzz, nazp[p]);
            MUL2(zz, dz, dz);
            FMA2(d2, dy, dy, zz);
            FMA2(d2, dx, dx, d2);
            unsigned dlo, dhi;
            UNPACK2(dlo, dhi, d2);
            {   // anchor 2p
                bool in = __uint_as_float(dlo) < 0.04f;
                unsigned msk = __ballot_sync(0xffffffffu, in);
                int pos = cnt[2*p] + __popc(msk & lm);
                if (in && pos < KSn) candw[(2*p) * 32 + pos] = j;
                cnt[2*p] += __popc(msk);
            }
            {   // anchor 2p+1
                bool in = __uint_as_float(dhi) < 0.04f;
                unsigned msk = __ballot_sync(0xffffffffu, in);
                int pos = cnt[2*p + 1] + __popc(msk & lm);
                if (in && pos < KSn) candw[(2*p + 1) * 32 + pos] = j;
                cnt[2*p + 1] += __popc(msk);
            }
        }
    }
    __syncwarp();
#pragma unroll
    for (int aa = 0; aa < 8; ++aa) {
        int cc = cnt[aa] < KSn ? cnt[aa] : KSn;
        int fill0 = (cc > 0) ? candw[aa * 32] : 0;
        __syncwarp();
        if (lane >= cc) candw[aa * 32 + lane] = fill0;
    }
    __syncwarp();

    // --- factored moment: T = sum f*p ; F = sum f ; S = T - a*F ---
    for (int aa = 0; aa < 8; ++aa) {
        int a_local = wid * 8 + aa;
        float axx = abase[3*aa], ayy = abase[3*aa+1], azz = abase[3*aa+2];
        float t0 = 0.f, t1 = 0.f, t2 = 0.f, fs = 0.f;
#pragma unroll 8
        for (int k = 0; k < KSn; ++k) {
            int j = candw[aa * 32 + k];
            float4 p = npts[j];
            float fv = __ldg(&fb[(size_t)j * Cn + lane]);
            t0 = fmaf(fv, p.x, t0);
            t1 = fmaf(fv, p.y, t1);
            t2 = fmaf(fv, p.z, t2);
            fs += fv;
        }
        Ssm[a_local * 96 + lane * 3 + 0] = fmaf(-axx, fs, t0);
        Ssm[a_local * 96 + lane * 3 + 1] = fmaf(-ayy, fs, t1);
        Ssm[a_local * 96 + lane * 3 + 2] = fmaf(-azz, fs, t2);
    }
    __syncthreads();

    // --- GEMM: out[64 o][128 a] = W2[64][96] @ S^T, packed over k (f32x2) ---
    int o0 = (tid & 15) * 4;
    int aq = (tid >> 4) * 4;
    unsigned long long acc2[4][4] = {};
    for (int i = 0; i < 96; i += 4) {
        ulonglong2 w2[4], s2[4];
#pragma unroll
        for (int q = 0; q < 4; ++q)
            w2[q] = __ldg((const ulonglong2*)&g_W2[(o0 + q) * 96 + i]);
#pragma unroll
        for (int r = 0; r < 4; ++r)
            s2[r] = *(const ulonglong2*)&Ssm[(aq + r) * 96 + i];
#pragma unroll
        for (int q = 0; q < 4; ++q)
#pragma unroll
            for (int r = 0; r < 4; ++r) {
                FMA2(acc2[q][r], w2[q].x, s2[r].x, acc2[q][r]);
                FMA2(acc2[q][r], w2[q].y, s2[r].y, acc2[q][r]);
            }
    }
#pragma unroll
    for (int q = 0; q < 4; ++q)
#pragma unroll
        for (int r = 0; r < 4; ++r) {
            unsigned lo, hi;
            UNPACK2(lo, hi, acc2[q][r]);
            g_x[((size_t)f * KMn + o * MIDn + o0 + q) * Mn + tile * 128 + aq + r] =
                __uint_as_float(lo) + __uint_as_float(hi);
        }
}

// ---------------------------------------------------------------------------
// 4) BN stats per (l, km) over 4096 values, float4 vectorized
// ---------------------------------------------------------------------------
__global__ void stats_kernel() {
    int pair = blockIdx.x;
    int l = pair / KMn, km = pair % KMn;
    int tid = threadIdx.x;
    float s1 = 0.f, s2 = 0.f;
#pragma unroll
    for (int b = 0; b < Bn; ++b) {
        const float4* row = (const float4*)(g_x + ((size_t)((b * Ln + l) * KMn + km)) * Mn);
#pragma unroll
        for (int m = 0; m < 2; ++m) {
            float4 v = row[tid + m * 128];
            s1 += v.x + v.y + v.z + v.w;
            s2 += v.x*v.x + v.y*v.y + v.z*v.z + v.w*v.w;
        }
    }
    __shared__ float sh1[4], sh2[4];
#pragma unroll
    for (int off = 16; off > 0; off >>= 1) {
        s1 += __shfl_down_sync(0xffffffffu, s1, off);
        s2 += __shfl_down_sync(0xffffffffu, s2, off);
    }
    int lane = tid & 31, w = tid >> 5;
    if (lane == 0) { sh1[w] = s1; sh2[w] = s2; }
    __syncthreads();
    if (tid == 0) {
        float t1 = sh1[0] + sh1[1] + sh1[2] + sh1[3];
        float t2 = sh2[0] + sh2[1] + sh2[2] + sh2[3];
        float mean = t1 * (1.f / 4096.f);
        float var  = t2 * (1.f / 4096.f) - mean * mean;
        g_mean[pair] = mean;
        g_rstd[pair] = rsqrtf(var + 1e-5f);
    }
}

// ---------------------------------------------------------------------------
// 5) Fused BN + ReLU + temporal GEMM; inner product in packed f32x2
// ---------------------------------------------------------------------------
__global__ void __launch_bounds__(256)
bn_gemm_kernel(const float* __restrict__ gamma, const float* __restrict__ beta,
               const float* __restrict__ tw, float* __restrict__ dout)
{
    extern __shared__ float smf[];
    float* xsm  = smf;           // [192][128]
    float* twsm = smf + 24576;   // [128][192]

    int f = blockIdx.y, l = f & 7;
    int mb = blockIdx.x * 128;
    int tid = threadIdx.x;

    for (int idx = tid; idx < KMn * 128; idx += 256) {
        int k = idx >> 7, m = idx & 127;
        float v  = g_x[((size_t)f * KMn + k) * Mn + mb + m];
        float xn = (v - g_mean[l * KMn + k]) * g_rstd[l * KMn + k] * gamma[k] + beta[k];
        xsm[idx] = fmaxf(xn, 0.f);
    }
    for (int idx = tid; idx < OUTn * KMn; idx += 256) twsm[idx] = tw[idx];
    __syncthreads();

    int o0 = (tid >> 4) * 8;
    int m0 = (tid & 15) * 8;
    unsigned long long acc2[8][4] = {};
    for (int k = 0; k < KMn; k += 4) {
        float4 wv[8];
#pragma unroll
        for (int q = 0; q < 8; ++q) wv[q] = *(const float4*)&twsm[(o0 + q) * KMn + k];
        ulonglong2 xv0[4], xv1[4];
#pragma unroll
        for (int j = 0; j < 4; ++j) {
            xv0[j] = *(const ulonglong2*)&xsm[(k + j) * 128 + m0];
            xv1[j] = *(const ulonglong2*)&xsm[(k + j) * 128 + m0 + 4];
        }
#pragma unroll
        for (int q = 0; q < 8; ++q) {
            const float* wq = (const float*)&wv[q];
#pragma unroll
            for (int j = 0; j < 4; ++j) {
                unsigned wb = __float_as_uint(wq[j]);
                unsigned long long ww;
                PACK2(ww, wb, wb);
                FMA2(acc2[q][0], ww, xv0[j].x, acc2[q][0]);
                FMA2(acc2[q][1], ww, xv0[j].y, acc2[q][1]);
                FMA2(acc2[q][2], ww, xv1[j].x, acc2[q][2]);
                FMA2(acc2[q][3], ww, xv1[j].y, acc2[q][3]);
            }
        }
    }
    float* outb = dout + (size_t)BLn * Mn * 3 + ((size_t)f * OUTn) * Mn + mb;
#pragma unroll
    for (int q = 0; q < 8; ++q)
#pragma unroll
        for (int r = 0; r < 4; ++r) {
            unsigned lo, hi;
            UNPACK2(lo, hi, acc2[q][r]);
            outb[(size_t)(o0 + q) * Mn + m0 + 2*r]     = __uint_as_float(lo);
            outb[(size_t)(o0 + q) * Mn + m0 + 2*r + 1] = __uint_as_float(hi);
        }
}

// ---------------------------------------------------------------------------
extern "C" void kernel_launch(void* const* d_in, const int* in_sizes, int n_in,
                              void* d_out, int out_size) {
    const float* xyzs     = (const float*)d_in[0];
    const float* features = (const float*)d_in[1];
    const float* cdw      = (const float*)d_in[2];
    const float* cfw      = (const float*)d_in[3];
    const float* gamma    = (const float*)d_in[4];
    const float* beta     = (const float*)d_in[5];
    const float* tw       = (const float*)d_in[6];
    float* out = (float*)d_out;

    cudaFuncSetAttribute(group_conv_kernel, cudaFuncAttributeMaxDynamicSharedMemorySize, 98304);
    cudaFuncSetAttribute(bn_gemm_kernel,    cudaFuncAttributeMaxDynamicSharedMemorySize, 196608);

    transpose_feat_kernel<<<dim3(64, 32), dim3(32, 32)>>>(features, cdw, cfw);
    nop_kernel<<<1, 32>>>();   // keep group_conv as the profiled (4th) launch
    fps_kernel<<<32, 128>>>(xyzs, out);
    group_conv_kernel<<<dim3(8, 3, 32), 512, 98304>>>(xyzs, out);
    stats_kernel<<<Ln * KMn, 128>>>();
    bn_gemm_kernel<<<dim3(8, 32), 256, 196608>>>(gamma, beta, tw, out);
}

// round 14
// speedup vs baseline: 1.2515x; 1.2515x over previous
#include <cuda_runtime.h>
#include <cstdint>

#define Bn   4
#define Ln   8
#define Nn   2048
#define Cn   32
#define MIDn 64
#define OUTn 128
#define Mn   1024
#define KSn  32
#define KMn  192
#define BLn  32
#define FLTMAXC 3.4028234663852886e38f

#define MUL2(out, a, b) asm("mul.rn.f32x2 %0, %1, %2;" : "=l"(out) : "l"(a), "l"(b))
#define ADD2(out, a, b) asm("add.rn.f32x2 %0, %1, %2;" : "=l"(out) : "l"(a), "l"(b))
#define FMA2(out, a, b, c) asm("fma.rn.f32x2 %0, %1, %2, %3;" : "=l"(out) : "l"(a), "l"(b), "l"(c))
#define PACK2(out, lo, hi) asm("mov.b64 %0, {%1, %2};" : "=l"(out) : "r"(lo), "r"(hi))
#define UNPACK2(lo, hi, in) asm("mov.b64 {%0, %1}, %2;" : "=r"(lo), "=r"(hi) : "l"(in))
#define BAR128() asm volatile("bar.sync 1, 128;" ::: "memory")

__device__ float g_ft[BLn * Nn * Cn];
__device__ float g_x[Bn * Ln * KMn * Mn];
__device__ float g_W2[MIDn * 96];
__device__ float g_mean[Ln * KMn];
__device__ float g_rstd[Ln * KMn];
__device__ int   g_prog[BLn];

__global__ void nop_kernel() {}

// ---------------------------------------------------------------------------
// 1) Transpose features; block(0,0) builds W2; block(1,0) resets g_prog
// ---------------------------------------------------------------------------
__global__ void transpose_feat_kernel(const float* __restrict__ feat,
                                      const float* __restrict__ cdw,
                                      const float* __restrict__ cfw) {
    __shared__ float sm[32][33];
    int f  = blockIdx.y;
    int n0 = blockIdx.x * 32;
    int tx = threadIdx.x, ty = threadIdx.y;
    sm[ty][tx] = feat[((size_t)f * Cn + ty) * Nn + n0 + tx];
    if (blockIdx.x == 0 && blockIdx.y == 0) {
        int tid = ty * 32 + tx;
        for (int idx = tid; idx < MIDn * 96; idx += 1024) {
            int oo = idx / 96, r = idx % 96, c = r / 3, d = r % 3;
            g_W2[idx] = cfw[oo * Cn + c] * cdw[oo * 3 + d];
        }
    }
    if (blockIdx.x == 1 && blockIdx.y == 0) {
        int tid = ty * 32 + tx;
        if (tid < BLn) g_prog[tid] = 0;
    }
    __syncthreads();
    g_ft[((size_t)f * Nn + n0 + ty) * Cn + tx] = sm[tx][ty];
}

// ---------------------------------------------------------------------------
// 2) FUSED kernel: blocks 0-31 run FPS (producer), blocks 32-799 run
//    ball-query + grouped conv (consumers), pipelined via g_prog.
// ---------------------------------------------------------------------------
__global__ void __launch_bounds__(512)
fused_kernel(const float* __restrict__ xyz,
             float* __restrict__ dout)
{
    extern __shared__ char smraw[];
    __shared__ unsigned long long pk[2][4];

    int bid = blockIdx.x;
    int tid = threadIdx.x, lane = tid & 31, wid = tid >> 5;

    // ======================= FPS producer blocks =======================
    if (bid < BLn) {
        if (tid >= 128) return;          // warps 4-15 exit
        float4* pts = (float4*)smraw;    // 32 KB
        int f = bid;

        const float* base = xyz + (size_t)f * Nn * 3;
        for (int p = tid; p < Nn; p += 128)
            pts[p] = make_float4(base[3*p], base[3*p+1], base[3*p+2], 0.f);
        BAR128();

        unsigned long long px2[8], py2[8], pz2[8];
        float md[16];
#pragma unroll
        for (int q = 0; q < 8; ++q) {
            float4 a = pts[tid + (2*q) * 128];
            float4 b = pts[tid + (2*q+1) * 128];
            PACK2(px2[q], __float_as_uint(a.x), __float_as_uint(b.x));
            PACK2(py2[q], __float_as_uint(a.y), __float_as_uint(b.y));
            PACK2(pz2[q], __float_as_uint(a.z), __float_as_uint(b.z));
            md[2*q] = FLTMAXC; md[2*q+1] = FLTMAXC;
        }
        float sx = pts[0].x, sy = pts[0].y, sz = pts[0].z;

        for (int i = 0; i < Mn; ++i) {
            if (tid == 0) {
                float* o = dout + ((size_t)f * Mn + i) * 3;
                o[0] = sx; o[1] = sy; o[2] = sz;
                if ((i & 127) == 127) {          // publish a finished tile
                    __threadfence();
                    atomicExch(&g_prog[f], i + 1);
                }
            }

            unsigned long long nsx2, nsy2, nsz2;
            unsigned nx = __float_as_uint(-sx), ny = __float_as_uint(-sy), nz = __float_as_uint(-sz);
            PACK2(nsx2, nx, nx); PACK2(nsy2, ny, ny); PACK2(nsz2, nz, nz);

            float nv[16];
#pragma unroll
            for (int q = 0; q < 8; ++q) {
                unsigned long long dx, dy, dz, zz, d2;
                ADD2(dx, px2[q], nsx2);
                ADD2(dy, py2[q], nsy2);
                ADD2(dz, pz2[q], nsz2);
                MUL2(zz, dz, dz);
                FMA2(d2, dy, dy, zz);
                FMA2(d2, dx, dx, d2);
                unsigned ulo, uhi;
                UNPACK2(ulo, uhi, d2);
                float nmlo = fminf(md[2*q],   __uint_as_float(ulo));
                float nmhi = fminf(md[2*q+1], __uint_as_float(uhi));
                md[2*q] = nmlo; md[2*q+1] = nmhi;
                nv[2*q] = nmlo; nv[2*q+1] = nmhi;
            }
            float tv[8]; int ti[8];
#pragma unroll
            for (int q = 0; q < 8; ++q) {
                bool c = nv[2*q] >= nv[2*q+1];
                tv[q] = c ? nv[2*q] : nv[2*q+1];
                ti[q] = c ? 2*q : 2*q+1;
            }
#pragma unroll
            for (int q = 0; q < 4; ++q) {
                bool c = tv[2*q] >= tv[2*q+1];
                tv[q] = c ? tv[2*q] : tv[2*q+1];
                ti[q] = c ? ti[2*q] : ti[2*q+1];
            }
            bool c0 = tv[0] >= tv[1];
            float va = c0 ? tv[0] : tv[1];
            int   ia = c0 ? ti[0] : ti[1];
            bool c1 = tv[2] >= tv[3];
            float vb = c1 ? tv[2] : tv[3];
            int   ib = c1 ? ti[2] : ti[3];
            bool cf = va >= vb;
            float bvv = cf ? va : vb;
            int   bj  = cf ? ia : ib;
            unsigned bi = (unsigned)(tid + bj * 128);

            unsigned vbits = __float_as_uint(bvv);
            unsigned wmax  = __reduce_max_sync(0xffffffffu, vbits);
            unsigned cidx  = (vbits == wmax) ? bi : 0xffffffffu;
            unsigned widx  = __reduce_min_sync(0xffffffffu, cidx);

            int s = i & 1;
            if (lane == 0)
                pk[s][wid] = ((unsigned long long)wmax << 32) |
                             (unsigned long long)(~widx);
            BAR128();

            unsigned long long m0 = pk[s][0], m1 = pk[s][1];
            unsigned long long m2 = pk[s][2], m3 = pk[s][3];
            unsigned long long ma = (m0 > m1) ? m0 : m1;
            unsigned long long mb = (m2 > m3) ? m2 : m3;
            unsigned long long mm = (ma > mb) ? ma : mb;
            int idx = (int)(~(unsigned)mm);
            float4 spv = pts[idx];
            sx = spv.x; sy = spv.y; sz = spv.z;
        }
        return;
    }

    // ======================= group-conv consumer blocks =======================
    float4* npts = (float4*)smraw;                  // 32768 B
    float*  Ssm  = (float*)(smraw + 32768);         // 49152 B
    int*    cand = (int*)(smraw + 32768 + 49152);   // 16384 B

    int g    = bid - BLn;
    int tile = g / 96;          // tile-major: early tiles get wave-1 slots
    int rem  = g % 96;
    int o    = rem >> 5;
    int f    = rem & 31;
    int b = f >> 3, l = f & 7;

    int ln = l + o - 1;
    if (ln < 0 || ln >= Ln) {
        for (int idx = tid; idx < MIDn * 128; idx += 512) {
            int kk = idx >> 7, mm = idx & 127;
            g_x[((size_t)f * KMn + o * MIDn + kk) * Mn + tile * 128 + mm] = 0.f;
        }
        return;
    }
    int nbr = b * Ln + ln;

    const float* nb = xyz + (size_t)nbr * Nn * 3;
    for (int p = tid; p < Nn; p += 512)
        npts[p] = make_float4(nb[3*p], nb[3*p+1], nb[3*p+2], 0.f);

    // wait for this tile's anchors
    if (tid == 0) {
        volatile int* vp = &g_prog[f];
        int need = (tile + 1) * 128;
        while (*vp < need) __nanosleep(200);
        __threadfence();
    }
    __syncthreads();

    int* candw = cand + wid * 256;
    const float* fb = g_ft + (size_t)nbr * Nn * Cn;
    unsigned lm = (1u << lane) - 1u;
    const float* abase = dout + ((size_t)f * Mn + tile * 128 + wid * 8) * 3;

    unsigned long long naxp[4], nayp[4], nazp[4];
    int cnt[8];
#pragma unroll
    for (int p = 0; p < 4; ++p) {
        PACK2(naxp[p], __float_as_uint(-abase[6*p    ]), __float_as_uint(-abase[6*p + 3]));
        PACK2(nayp[p], __float_as_uint(-abase[6*p + 1]), __float_as_uint(-abase[6*p + 4]));
        PACK2(nazp[p], __float_as_uint(-abase[6*p + 2]), __float_as_uint(-abase[6*p + 5]));
        cnt[2*p] = 0; cnt[2*p + 1] = 0;
    }
    for (int basej = 0; basej < Nn; basej += 32) {
        int cmin = cnt[0];
#pragma unroll
        for (int aa = 1; aa < 8; ++aa) cmin = cnt[aa] < cmin ? cnt[aa] : cmin;
        if (cmin >= KSn) break;
        int j = basej + lane;
        float4 pt = npts[j];
        unsigned long long pxx, pyy, pzz;
        PACK2(pxx, __float_as_uint(pt.x), __float_as_uint(pt.x));
        PACK2(pyy, __float_as_uint(pt.y), __float_as_uint(pt.y));
        PACK2(pzz, __float_as_uint(pt.z), __float_as_uint(pt.z));
#pragma unroll
        for (int p = 0; p < 4; ++p) {
            if (cnt[2*p] >= KSn && cnt[2*p + 1] >= KSn) continue;
            unsigned long long dx, dy, dz, zz, d2;
            ADD2(dx, pxx, naxp[p]);
            ADD2(dy, pyy, nayp[p]);
            ADD2(dz, pzz, nazp[p]);
            MUL2(zz, dz, dz);
            FMA2(d2, dy, dy, zz);
            FMA2(d2, dx, dx, d2);
            unsigned dlo, dhi;
            UNPACK2(dlo, dhi, d2);
            {
                bool in = __uint_as_float(dlo) < 0.04f;
                unsigned msk = __ballot_sync(0xffffffffu, in);
                int pos = cnt[2*p] + __popc(msk & lm);
                if (in && pos < KSn) candw[(2*p) * 32 + pos] = j;
                cnt[2*p] += __popc(msk);
            }
            {
                bool in = __uint_as_float(dhi) < 0.04f;
                unsigned msk = __ballot_sync(0xffffffffu, in);
                int pos = cnt[2*p + 1] + __popc(msk & lm);
                if (in && pos < KSn) candw[(2*p + 1) * 32 + pos] = j;
                cnt[2*p + 1] += __popc(msk);
            }
        }
    }
    __syncwarp();
#pragma unroll
    for (int aa = 0; aa < 8; ++aa) {
        int cc = cnt[aa] < KSn ? cnt[aa] : KSn;
        int fill0 = (cc > 0) ? candw[aa * 32] : 0;
        __syncwarp();
        if (lane >= cc) candw[aa * 32 + lane] = fill0;
    }
    __syncwarp();

    for (int aa = 0; aa < 8; ++aa) {
        int a_local = wid * 8 + aa;
        float axx = abase[3*aa], ayy = abase[3*aa+1], azz = abase[3*aa+2];
        float t0 = 0.f, t1 = 0.f, t2 = 0.f, fs = 0.f;
#pragma unroll 8
        for (int k = 0; k < KSn; ++k) {
            int j = candw[aa * 32 + k];
            float4 p = npts[j];
            float fv = __ldg(&fb[(size_t)j * Cn + lane]);
            t0 = fmaf(fv, p.x, t0);
            t1 = fmaf(fv, p.y, t1);
            t2 = fmaf(fv, p.z, t2);
            fs += fv;
        }
        Ssm[a_local * 96 + lane * 3 + 0] = fmaf(-axx, fs, t0);
        Ssm[a_local * 96 + lane * 3 + 1] = fmaf(-ayy, fs, t1);
        Ssm[a_local * 96 + lane * 3 + 2] = fmaf(-azz, fs, t2);
    }
    __syncthreads();

    int o0 = (tid & 15) * 4;
    int aq = (tid >> 4) * 4;
    float acc[4][4] = {};
    for (int i = 0; i < 96; i += 4) {
        float4 w[4], s[4];
#pragma unroll
        for (int q = 0; q < 4; ++q) w[q] = __ldg((const float4*)&g_W2[(o0 + q) * 96 + i]);
#pragma unroll
        for (int r = 0; r < 4; ++r) s[r] = *(const float4*)&Ssm[(aq + r) * 96 + i];
#pragma unroll
        for (int q = 0; q < 4; ++q)
#pragma unroll
            for (int r = 0; r < 4; ++r)
                acc[q][r] += w[q].x * s[r].x + w[q].y * s[r].y
                           + w[q].z * s[r].z + w[q].w * s[r].w;
    }
#pragma unroll
    for (int q = 0; q < 4; ++q)
#pragma unroll
        for (int r = 0; r < 4; ++r)
            g_x[((size_t)f * KMn + o * MIDn + o0 + q) * Mn + tile * 128 + aq + r] = acc[q][r];
}

// ---------------------------------------------------------------------------
// 4) BN stats per (l, km) over 4096 values, float4 vectorized
// ---------------------------------------------------------------------------
__global__ void stats_kernel() {
    int pair = blockIdx.x;
    int l = pair / KMn, km = pair % KMn;
    int tid = threadIdx.x;
    float s1 = 0.f, s2 = 0.f;
#pragma unroll
    for (int b = 0; b < Bn; ++b) {
        const float4* row = (const float4*)(g_x + ((size_t)((b * Ln + l) * KMn + km)) * Mn);
#pragma unroll
        for (int m = 0; m < 2; ++m) {
            float4 v = row[tid + m * 128];
            s1 += v.x + v.y + v.z + v.w;
            s2 += v.x*v.x + v.y*v.y + v.z*v.z + v.w*v.w;
        }
    }
    __shared__ float sh1[4], sh2[4];
#pragma unroll
    for (int off = 16; off > 0; off >>= 1) {
        s1 += __shfl_down_sync(0xffffffffu, s1, off);
        s2 += __shfl_down_sync(0xffffffffu, s2, off);
    }
    int lane = tid & 31, w = tid >> 5;
    if (lane == 0) { sh1[w] = s1; sh2[w] = s2; }
    __syncthreads();
    if (tid == 0) {
        float t1 = sh1[0] + sh1[1] + sh1[2] + sh1[3];
        float t2 = sh2[0] + sh2[1] + sh2[2] + sh2[3];
        float mean = t1 * (1.f / 4096.f);
        float var  = t2 * (1.f / 4096.f) - mean * mean;
        g_mean[pair] = mean;
        g_rstd[pair] = rsqrtf(var + 1e-5f);
    }
}

// ---------------------------------------------------------------------------
// 5) Fused BN + ReLU + temporal GEMM; inner product in packed f32x2
// ---------------------------------------------------------------------------
__global__ void __launch_bounds__(256)
bn_gemm_kernel(const float* __restrict__ gamma, const float* __restrict__ beta,
               const float* __restrict__ tw, float* __restrict__ dout)
{
    extern __shared__ float smf[];
    float* xsm  = smf;           // [192][128]
    float* twsm = smf + 24576;   // [128][192]

    int f = blockIdx.y, l = f & 7;
    int mb = blockIdx.x * 128;
    int tid = threadIdx.x;

    for (int idx = tid; idx < KMn * 128; idx += 256) {
        int k = idx >> 7, m = idx & 127;
        float v  = g_x[((size_t)f * KMn + k) * Mn + mb + m];
        float xn = (v - g_mean[l * KMn + k]) * g_rstd[l * KMn + k] * gamma[k] + beta[k];
        xsm[idx] = fmaxf(xn, 0.f);
    }
    for (int idx = tid; idx < OUTn * KMn; idx += 256) twsm[idx] = tw[idx];
    __syncthreads();

    int o0 = (tid >> 4) * 8;
    int m0 = (tid & 15) * 8;
    unsigned long long acc2[8][4] = {};
    for (int k = 0; k < KMn; k += 4) {
        float4 wv[8];
#pragma unroll
        for (int q = 0; q < 8; ++q) wv[q] = *(const float4*)&twsm[(o0 + q) * KMn + k];
        ulonglong2 xv0[4], xv1[4];
#pragma unroll
        for (int j = 0; j < 4; ++j) {
            xv0[j] = *(const ulonglong2*)&xsm[(k + j) * 128 + m0];
            xv1[j] = *(const ulonglong2*)&xsm[(k + j) * 128 + m0 + 4];
        }
#pragma unroll
        for (int q = 0; q < 8; ++q) {
            const float* wq = (const float*)&wv[q];
#pragma unroll
            for (int j = 0; j < 4; ++j) {
                unsigned wb = __float_as_uint(wq[j]);
                unsigned long long ww;
                PACK2(ww, wb, wb);
                FMA2(acc2[q][0], ww, xv0[j].x, acc2[q][0]);
                FMA2(acc2[q][1], ww, xv0[j].y, acc2[q][1]);
                FMA2(acc2[q][2], ww, xv1[j].x, acc2[q][2]);
                FMA2(acc2[q][3], ww, xv1[j].y, acc2[q][3]);
            }
        }
    }
    float* outb = dout + (size_t)BLn * Mn * 3 + ((size_t)f * OUTn) * Mn + mb;
#pragma unroll
    for (int q = 0; q < 8; ++q)
#pragma unroll
        for (int r = 0; r < 4; ++r) {
            unsigned lo, hi;
            UNPACK2(lo, hi, acc2[q][r]);
            outb[(size_t)(o0 + q) * Mn + m0 + 2*r]     = __uint_as_float(lo);
            outb[(size_t)(o0 + q) * Mn + m0 + 2*r + 1] = __uint_as_float(hi);
        }
}

// ---------------------------------------------------------------------------
extern "C" void kernel_launch(void* const* d_in, const int* in_sizes, int n_in,
                              void* d_out, int out_size) {
    const float* xyzs     = (const float*)d_in[0];
    const float* features = (const float*)d_in[1];
    const float* cdw      = (const float*)d_in[2];
    const float* cfw      = (const float*)d_in[3];
    const float* gamma    = (const float*)d_in[4];
    const float* beta     = (const float*)d_in[5];
    const float* tw       = (const float*)d_in[6];
    float* out = (float*)d_out;

    cudaFuncSetAttribute(fused_kernel,   cudaFuncAttributeMaxDynamicSharedMemorySize, 98304);
    cudaFuncSetAttribute(bn_gemm_kernel, cudaFuncAttributeMaxDynamicSharedMemorySize, 196608);

    transpose_feat_kernel<<<dim3(64, 32), dim3(32, 32)>>>(features, cdw, cfw);
    nop_kernel<<<1, 32>>>();   // keep the fused kernel as the profiled (4th)
    nop_kernel<<<1, 32>>>();   // launch for ncu -s 5 -c 1
    fused_kernel<<<32 + 768, 512, 98304>>>(xyzs, out);
    stats_kernel<<<Ln * KMn, 128>>>();
    bn_gemm_kernel<<<dim3(8, 32), 256, 196608>>>(gamma, beta, tw, out);
}

// round 15
// speedup vs baseline: 1.2721x; 1.0165x over previous
#include <cuda_runtime.h>
#include <cstdint>

#define Bn   4
#define Ln   8
#define Nn   2048
#define Cn   32
#define MIDn 64
#define OUTn 128
#define Mn   1024
#define KSn  32
#define KMn  192
#define BLn  32
#define FLTMAXC 3.4028234663852886e38f

#define MUL2(out, a, b) asm("mul.rn.f32x2 %0, %1, %2;" : "=l"(out) : "l"(a), "l"(b))
#define ADD2(out, a, b) asm("add.rn.f32x2 %0, %1, %2;" : "=l"(out) : "l"(a), "l"(b))
#define FMA2(out, a, b, c) asm("fma.rn.f32x2 %0, %1, %2, %3;" : "=l"(out) : "l"(a), "l"(b), "l"(c))
#define PACK2(out, lo, hi) asm("mov.b64 %0, {%1, %2};" : "=l"(out) : "r"(lo), "r"(hi))
#define UNPACK2(lo, hi, in) asm("mov.b64 {%0, %1}, %2;" : "=r"(lo), "=r"(hi) : "l"(in))
#define BAR128() asm volatile("bar.sync 1, 128;" ::: "memory")

__device__ float g_ft[BLn * Nn * Cn];
__device__ float g_x[Bn * Ln * KMn * Mn];
__device__ float g_W2[MIDn * 96];
__device__ float g_mean[Ln * KMn];
__device__ float g_rstd[Ln * KMn];
__device__ int   g_prog[BLn];

__global__ void nop_kernel() {}

// ---------------------------------------------------------------------------
// 1) Transpose features; block(0,0) builds W2; block(1,0) resets g_prog
// ---------------------------------------------------------------------------
__global__ void transpose_feat_kernel(const float* __restrict__ feat,
                                      const float* __restrict__ cdw,
                                      const float* __restrict__ cfw) {
    __shared__ float sm[32][33];
    int f  = blockIdx.y;
    int n0 = blockIdx.x * 32;
    int tx = threadIdx.x, ty = threadIdx.y;
    sm[ty][tx] = feat[((size_t)f * Cn + ty) * Nn + n0 + tx];
    if (blockIdx.x == 0 && blockIdx.y == 0) {
        int tid = ty * 32 + tx;
        for (int idx = tid; idx < MIDn * 96; idx += 1024) {
            int oo = idx / 96, r = idx % 96, c = r / 3, d = r % 3;
            g_W2[idx] = cfw[oo * Cn + c] * cdw[oo * 3 + d];
        }
    }
    if (blockIdx.x == 1 && blockIdx.y == 0) {
        int tid = ty * 32 + tx;
        if (tid < BLn) g_prog[tid] = 0;
    }
    __syncthreads();
    g_ft[((size_t)f * Nn + n0 + ty) * Cn + tx] = sm[tx][ty];
}

// ---------------------------------------------------------------------------
// 2) FUSED kernel: blocks 0-31 run FPS (producer), blocks 32-799 run
//    ball-query + grouped conv (consumers), pipelined via g_prog.
// ---------------------------------------------------------------------------
__global__ void __launch_bounds__(512)
fused_kernel(const float* __restrict__ xyz,
             float* __restrict__ dout)
{
    extern __shared__ char smraw[];
    __shared__ unsigned long long pk[2][4];

    int bid = blockIdx.x;
    int tid = threadIdx.x, lane = tid & 31, wid = tid >> 5;

    // ======================= FPS producer blocks =======================
    if (bid < BLn) {
        if (tid >= 128) return;          // warps 4-15 exit
        float4* pts = (float4*)smraw;    // 32 KB
        int f = bid;

        const float* base = xyz + (size_t)f * Nn * 3;
        for (int p = tid; p < Nn; p += 128)
            pts[p] = make_float4(base[3*p], base[3*p+1], base[3*p+2], 0.f);
        BAR128();

        unsigned long long px2[8], py2[8], pz2[8];
        float md[16];
#pragma unroll
        for (int q = 0; q < 8; ++q) {
            float4 a = pts[tid + (2*q) * 128];
            float4 b = pts[tid + (2*q+1) * 128];
            PACK2(px2[q], __float_as_uint(a.x), __float_as_uint(b.x));
            PACK2(py2[q], __float_as_uint(a.y), __float_as_uint(b.y));
            PACK2(pz2[q], __float_as_uint(a.z), __float_as_uint(b.z));
            md[2*q] = FLTMAXC; md[2*q+1] = FLTMAXC;
        }
        float sx = pts[0].x, sy = pts[0].y, sz = pts[0].z;

        for (int i = 0; i < Mn; ++i) {
            if (tid == 0) {
                float* o = dout + ((size_t)f * Mn + i) * 3;
                o[0] = sx; o[1] = sy; o[2] = sz;
                if ((i & 127) == 127) {          // publish a finished tile
                    __threadfence();
                    atomicExch(&g_prog[f], i + 1);
                }
            }

            unsigned long long nsx2, nsy2, nsz2;
            unsigned nx = __float_as_uint(-sx), ny = __float_as_uint(-sy), nz = __float_as_uint(-sz);
            PACK2(nsx2, nx, nx); PACK2(nsy2, ny, ny); PACK2(nsz2, nz, nz);

            float nv[16];
#pragma unroll
            for (int q = 0; q < 8; ++q) {
                unsigned long long dx, dy, dz, zz, d2;
                ADD2(dx, px2[q], nsx2);
                ADD2(dy, py2[q], nsy2);
                ADD2(dz, pz2[q], nsz2);
                MUL2(zz, dz, dz);
                FMA2(d2, dy, dy, zz);
                FMA2(d2, dx, dx, d2);
                unsigned ulo, uhi;
                UNPACK2(ulo, uhi, d2);
                float nmlo = fminf(md[2*q],   __uint_as_float(ulo));
                float nmhi = fminf(md[2*q+1], __uint_as_float(uhi));
                md[2*q] = nmlo; md[2*q+1] = nmhi;
                nv[2*q] = nmlo; nv[2*q+1] = nmhi;
            }
            float tv[8]; int ti[8];
#pragma unroll
            for (int q = 0; q < 8; ++q) {
                bool c = nv[2*q] >= nv[2*q+1];
                tv[q] = c ? nv[2*q] : nv[2*q+1];
                ti[q] = c ? 2*q : 2*q+1;
            }
#pragma unroll
            for (int q = 0; q < 4; ++q) {
                bool c = tv[2*q] >= tv[2*q+1];
                tv[q] = c ? tv[2*q] : tv[2*q+1];
                ti[q] = c ? ti[2*q] : ti[2*q+1];
            }
            bool c0 = tv[0] >= tv[1];
            float va = c0 ? tv[0] : tv[1];
            int   ia = c0 ? ti[0] : ti[1];
            bool c1 = tv[2] >= tv[3];
            float vb = c1 ? tv[2] : tv[3];
            int   ib = c1 ? ti[2] : ti[3];
            bool cf = va >= vb;
            float bvv = cf ? va : vb;
            int   bj  = cf ? ia : ib;
            unsigned bi = (unsigned)(tid + bj * 128);

            unsigned vbits = __float_as_uint(bvv);
            unsigned wmax  = __reduce_max_sync(0xffffffffu, vbits);
            unsigned cidx  = (vbits == wmax) ? bi : 0xffffffffu;
            unsigned widx  = __reduce_min_sync(0xffffffffu, cidx);

            int s = i & 1;
            if (lane == 0)
                pk[s][wid] = ((unsigned long long)wmax << 32) |
                             (unsigned long long)(~widx);
            BAR128();

            unsigned long long m0 = pk[s][0], m1 = pk[s][1];
            unsigned long long m2 = pk[s][2], m3 = pk[s][3];
            unsigned long long ma = (m0 > m1) ? m0 : m1;
            unsigned long long mb = (m2 > m3) ? m2 : m3;
            unsigned long long mm = (ma > mb) ? ma : mb;
            int idx = (int)(~(unsigned)mm);
            float4 spv = pts[idx];
            sx = spv.x; sy = spv.y; sz = spv.z;
        }
        return;
    }

    // ======================= group-conv consumer blocks =======================
    float4* npts = (float4*)smraw;                  // 32768 B
    float*  Ssm  = (float*)(smraw + 32768);         // 49152 B
    int*    cand = (int*)(smraw + 32768 + 49152);   // 16384 B

    int g    = bid - BLn;
    int tile = g / 96;          // tile-major: early tiles get wave-1 slots
    int rem  = g % 96;
    int o    = rem >> 5;
    int f    = rem & 31;
    int b = f >> 3, l = f & 7;

    int ln = l + o - 1;
    if (ln < 0 || ln >= Ln) {
        for (int idx = tid; idx < MIDn * 128; idx += 512) {
            int kk = idx >> 7, mm = idx & 127;
            g_x[((size_t)f * KMn + o * MIDn + kk) * Mn + tile * 128 + mm] = 0.f;
        }
        return;
    }
    int nbr = b * Ln + ln;

    const float* nb = xyz + (size_t)nbr * Nn * 3;
    for (int p = tid; p < Nn; p += 512)
        npts[p] = make_float4(nb[3*p], nb[3*p+1], nb[3*p+2], 0.f);

    // wait for this tile's anchors
    if (tid == 0) {
        volatile int* vp = &g_prog[f];
        int need = (tile + 1) * 128;
        while (*vp < need) __nanosleep(200);
        __threadfence();
    }
    __syncthreads();

    int* candw = cand + wid * 256;
    const float* fb = g_ft + (size_t)nbr * Nn * Cn;
    unsigned lm = (1u << lane) - 1u;
    const float* abase = dout + ((size_t)f * Mn + tile * 128 + wid * 8) * 3;

    unsigned long long naxp[4], nayp[4], nazp[4];
    int cnt[8];
#pragma unroll
    for (int p = 0; p < 4; ++p) {
        PACK2(naxp[p], __float_as_uint(-abase[6*p    ]), __float_as_uint(-abase[6*p + 3]));
        PACK2(nayp[p], __float_as_uint(-abase[6*p + 1]), __float_as_uint(-abase[6*p + 4]));
        PACK2(nazp[p], __float_as_uint(-abase[6*p + 2]), __float_as_uint(-abase[6*p + 5]));
        cnt[2*p] = 0; cnt[2*p + 1] = 0;
    }
    for (int basej = 0; basej < Nn; basej += 32) {
        int cmin = cnt[0];
#pragma unroll
        for (int aa = 1; aa < 8; ++aa) cmin = cnt[aa] < cmin ? cnt[aa] : cmin;
        if (cmin >= KSn) break;
        int j = basej + lane;
        float4 pt = npts[j];
        unsigned long long pxx, pyy, pzz;
        PACK2(pxx, __float_as_uint(pt.x), __float_as_uint(pt.x));
        PACK2(pyy, __float_as_uint(pt.y), __float_as_uint(pt.y));
        PACK2(pzz, __float_as_uint(pt.z), __float_as_uint(pt.z));
#pragma unroll
        for (int p = 0; p < 4; ++p) {
            if (cnt[2*p] >= KSn && cnt[2*p + 1] >= KSn) continue;
            unsigned long long dx, dy, dz, zz, d2;
            ADD2(dx, pxx, naxp[p]);
            ADD2(dy, pyy, nayp[p]);
            ADD2(dz, pzz, nazp[p]);
            MUL2(zz, dz, dz);
            FMA2(d2, dy, dy, zz);
            FMA2(d2, dx, dx, d2);
            unsigned dlo, dhi;
            UNPACK2(dlo, dhi, d2);
            {
                bool in = __uint_as_float(dlo) < 0.04f;
                unsigned msk = __ballot_sync(0xffffffffu, in);
                int pos = cnt[2*p] + __popc(msk & lm);
                if (in && pos < KSn) candw[(2*p) * 32 + pos] = j;
                cnt[2*p] += __popc(msk);
            }
            {
                bool in = __uint_as_float(dhi) < 0.04f;
                unsigned msk = __ballot_sync(0xffffffffu, in);
                int pos = cnt[2*p + 1] + __popc(msk & lm);
                if (in && pos < KSn) candw[(2*p + 1) * 32 + pos] = j;
                cnt[2*p + 1] += __popc(msk);
            }
        }
    }
    __syncwarp();
#pragma unroll
    for (int aa = 0; aa < 8; ++aa) {
        int cc = cnt[aa] < KSn ? cnt[aa] : KSn;
        int fill0 = (cc > 0) ? candw[aa * 32] : 0;
        __syncwarp();
        if (lane >= cc) candw[aa * 32 + lane] = fill0;
    }
    __syncwarp();

    // --- factored moment; candidate indices fetched 4-at-a-time (int4) ---
    const int4* candw4 = (const int4*)candw;
    for (int aa = 0; aa < 8; ++aa) {
        int a_local = wid * 8 + aa;
        float axx = abase[3*aa], ayy = abase[3*aa+1], azz = abase[3*aa+2];
        float t0 = 0.f, t1 = 0.f, t2 = 0.f, fs = 0.f;
#pragma unroll
        for (int kq = 0; kq < 8; ++kq) {
            int4 c4 = candw4[aa * 8 + kq];
            {
                float4 p = npts[c4.x];
                float fv = __ldg(&fb[(size_t)c4.x * Cn + lane]);
                t0 = fmaf(fv, p.x, t0); t1 = fmaf(fv, p.y, t1);
                t2 = fmaf(fv, p.z, t2); fs += fv;
            }
            {
                float4 p = npts[c4.y];
                float fv = __ldg(&fb[(size_t)c4.y * Cn + lane]);
                t0 = fmaf(fv, p.x, t0); t1 = fmaf(fv, p.y, t1);
                t2 = fmaf(fv, p.z, t2); fs += fv;
            }
            {
                float4 p = npts[c4.z];
                float fv = __ldg(&fb[(size_t)c4.z * Cn + lane]);
                t0 = fmaf(fv, p.x, t0); t1 = fmaf(fv, p.y, t1);
                t2 = fmaf(fv, p.z, t2); fs += fv;
            }
            {
                float4 p = npts[c4.w];
                float fv = __ldg(&fb[(size_t)c4.w * Cn + lane]);
                t0 = fmaf(fv, p.x, t0); t1 = fmaf(fv, p.y, t1);
                t2 = fmaf(fv, p.z, t2); fs += fv;
            }
        }
        Ssm[a_local * 96 + lane * 3 + 0] = fmaf(-axx, fs, t0);
        Ssm[a_local * 96 + lane * 3 + 1] = fmaf(-ayy, fs, t1);
        Ssm[a_local * 96 + lane * 3 + 2] = fmaf(-azz, fs, t2);
    }
    __syncthreads();

    int o0 = (tid & 15) * 4;
    int aq = (tid >> 4) * 4;
    float acc[4][4] = {};
    for (int i = 0; i < 96; i += 4) {
        float4 w[4], s[4];
#pragma unroll
        for (int q = 0; q < 4; ++q) w[q] = __ldg((const float4*)&g_W2[(o0 + q) * 96 + i]);
#pragma unroll
        for (int r = 0; r < 4; ++r) s[r] = *(const float4*)&Ssm[(aq + r) * 96 + i];
#pragma unroll
        for (int q = 0; q < 4; ++q)
#pragma unroll
            for (int r = 0; r < 4; ++r)
                acc[q][r] += w[q].x * s[r].x + w[q].y * s[r].y
                           + w[q].z * s[r].z + w[q].w * s[r].w;
    }
#pragma unroll
    for (int q = 0; q < 4; ++q)
#pragma unroll
        for (int r = 0; r < 4; ++r)
            g_x[((size_t)f * KMn + o * MIDn + o0 + q) * Mn + tile * 128 + aq + r] = acc[q][r];
}

// ---------------------------------------------------------------------------
// 4) BN stats per (l, km) over 4096 values, float4 vectorized
// ---------------------------------------------------------------------------
__global__ void stats_kernel() {
    int pair = blockIdx.x;
    int l = pair / KMn, km = pair % KMn;
    int tid = threadIdx.x;
    float s1 = 0.f, s2 = 0.f;
#pragma unroll
    for (int b = 0; b < Bn; ++b) {
        const float4* row = (const float4*)(g_x + ((size_t)((b * Ln + l) * KMn + km)) * Mn);
#pragma unroll
        for (int m = 0; m < 2; ++m) {
            float4 v = row[tid + m * 128];
            s1 += v.x + v.y + v.z + v.w;
            s2 += v.x*v.x + v.y*v.y + v.z*v.z + v.w*v.w;
        }
    }
    __shared__ float sh1[4], sh2[4];
#pragma unroll
    for (int off = 16; off > 0; off >>= 1) {
        s1 += __shfl_down_sync(0xffffffffu, s1, off);
        s2 += __shfl_down_sync(0xffffffffu, s2, off);
    }
    int lane = tid & 31, w = tid >> 5;
    if (lane == 0) { sh1[w] = s1; sh2[w] = s2; }
    __syncthreads();
    if (tid == 0) {
        float t1 = sh1[0] + sh1[1] + sh1[2] + sh1[3];
        float t2 = sh2[0] + sh2[1] + sh2[2] + sh2[3];
        float mean = t1 * (1.f / 4096.f);
        float var  = t2 * (1.f / 4096.f) - mean * mean;
        g_mean[pair] = mean;
        g_rstd[pair] = rsqrtf(var + 1e-5f);
    }
}

// ---------------------------------------------------------------------------
// 5) Fused BN + ReLU + temporal GEMM; tw via __ldg (smem halves -> 2 blk/SM)
// ---------------------------------------------------------------------------
__global__ void __launch_bounds__(256)
bn_gemm_kernel(const float* __restrict__ gamma, const float* __restrict__ beta,
               const float* __restrict__ tw, float* __restrict__ dout)
{
    extern __shared__ float smf[];
    float* xsm = smf;            // [192][128] = 96 KB

    int f = blockIdx.y, l = f & 7;
    int mb = blockIdx.x * 128;
    int tid = threadIdx.x;

    for (int idx = tid; idx < KMn * 128; idx += 256) {
        int k = idx >> 7, m = idx & 127;
        float v  = g_x[((size_t)f * KMn + k) * Mn + mb + m];
        float xn = (v - g_mean[l * KMn + k]) * g_rstd[l * KMn + k] * gamma[k] + beta[k];
        xsm[idx] = fmaxf(xn, 0.f);
    }
    __syncthreads();

    int o0 = (tid >> 4) * 8;
    int m0 = (tid & 15) * 8;
    unsigned long long acc2[8][4] = {};
    for (int k = 0; k < KMn; k += 4) {
        float4 wv[8];
#pragma unroll
        for (int q = 0; q < 8; ++q)
            wv[q] = __ldg((const float4*)&tw[(o0 + q) * KMn + k]);
        ulonglong2 xv0[4], xv1[4];
#pragma unroll
        for (int j = 0; j < 4; ++j) {
            xv0[j] = *(const ulonglong2*)&xsm[(k + j) * 128 + m0];
            xv1[j] = *(const ulonglong2*)&xsm[(k + j) * 128 + m0 + 4];
        }
#pragma unroll
        for (int q = 0; q < 8; ++q) {
            const float* wq = (const float*)&wv[q];
#pragma unroll
            for (int j = 0; j < 4; ++j) {
                unsigned wb = __float_as_uint(wq[j]);
                unsigned long long ww;
                PACK2(ww, wb, wb);
                FMA2(acc2[q][0], ww, xv0[j].x, acc2[q][0]);
                FMA2(acc2[q][1], ww, xv0[j].y, acc2[q][1]);
                FMA2(acc2[q][2], ww, xv1[j].x, acc2[q][2]);
                FMA2(acc2[q][3], ww, xv1[j].y, acc2[q][3]);
            }
        }
    }
    float* outb = dout + (size_t)BLn * Mn * 3 + ((size_t)f * OUTn) * Mn + mb;
#pragma unroll
    for (int q = 0; q < 8; ++q)
#pragma unroll
        for (int r = 0; r < 4; ++r) {
            unsigned lo, hi;
            UNPACK2(lo, hi, acc2[q][r]);
            outb[(size_t)(o0 + q) * Mn + m0 + 2*r]     = __uint_as_float(lo);
            outb[(size_t)(o0 + q) * Mn + m0 + 2*r + 1] = __uint_as_float(hi);
        }
}

// ---------------------------------------------------------------------------
extern "C" void kernel_launch(void* const* d_in, const int* in_sizes, int n_in,
                              void* d_out, int out_size) {
    const float* xyzs     = (const float*)d_in[0];
    const float* features = (const float*)d_in[1];
    const float* cdw      = (const float*)d_in[2];
    const float* cfw      = (const float*)d_in[3];
    const float* gamma    = (const float*)d_in[4];
    const float* beta     = (const float*)d_in[5];
    const float* tw       = (const float*)d_in[6];
    float* out = (float*)d_out;

    cudaFuncSetAttribute(fused_kernel,   cudaFuncAttributeMaxDynamicSharedMemorySize, 98304);
    cudaFuncSetAttribute(bn_gemm_kernel, cudaFuncAttributeMaxDynamicSharedMemorySize, 98304);

    transpose_feat_kernel<<<dim3(64, 32), dim3(32, 32)>>>(features, cdw, cfw);
    nop_kernel<<<1, 32>>>();   // keep the fused kernel as the profiled (4th)
    nop_kernel<<<1, 32>>>();   // launch for ncu -s 5 -c 1
    fused_kernel<<<32 + 768, 512, 98304>>>(xyzs, out);
    stats_kernel<<<Ln * KMn, 128>>>();
    bn_gemm_kernel<<<dim3(8, 32), 256, 98304>>>(gamma, beta, tw, out);
}